// round 1
// baseline (speedup 1.0000x reference)
#include <cuda_runtime.h>

// Problem constants (from setup_inputs): B=2, Nr=40962, Nh=4*Nr-6, Cin=128, Co=64
#define BB      2
#define NR      40962
#define NHH     163842
#define M_UP    (BB*NR)        // 81924 rows for up GEMM
#define M_CONV  (BB*NHH)       // 327684 rows for conv GEMMs
#define CIN     128
#define CO      64
#define NPART   256

// Scratch (device globals: allocation-guard safe)
__device__ float g_h[BB*NR*448];          // up-GEMM output, viewed as [B, Nr*7, 64]
__device__ float g_xcat[BB*NHH*CIN];      // concat(x1_up, x2) : [B, Nh, 128]
__device__ float g_y1[BB*NHH*CO];         // conv1 raw output (pre-BN)
__device__ float g_part[NPART*2*CO];      // BN partial sums
__device__ float g_bn[2*CO];              // fused BN params: scale[64], shift[64]

// ---------------------------------------------------------------------------
// Up-projection GEMM: g_h[r, col] = x1[r, :] @ up_W[:, col] + up_b[col]
// M=81924, N=448 (7 col-tiles of 64), K=128 (2 sub-chunks of 64)
// ---------------------------------------------------------------------------
__global__ __launch_bounds__(256) void gemm_up_kernel(
    const float* __restrict__ x1, const float* __restrict__ W,
    const float* __restrict__ bias)
{
    __shared__ float As[64*68];
    __shared__ float Ws[64*64];
    const int tid = threadIdx.x;
    const int tx = tid & 15, ty = tid >> 4;
    const int row0 = blockIdx.x * 64;
    const int col0 = blockIdx.y * 64;
    float acc[4][4] = {};

    for (int half = 0; half < 2; half++) {
        __syncthreads();
        // A tile: 64 rows x 64 cols (coalesced float4)
        for (int idx = tid; idx < 64*16; idx += 256) {
            int r = idx >> 4, q = idx & 15;
            int gr = row0 + r; if (gr >= M_UP) gr = M_UP - 1;
            *(float4*)&As[r*68 + q*4] =
                *(const float4*)&x1[(size_t)gr*128 + half*64 + q*4];
        }
        // W tile: [64 k][64 cols], up_W layout [128, 448]
        for (int idx = tid; idx < 64*16; idx += 256) {
            int c = idx >> 4, q = idx & 15;
            *(float4*)&Ws[c*64 + q*4] =
                *(const float4*)&W[(size_t)(half*64 + c)*448 + col0 + q*4];
        }
        __syncthreads();
        #pragma unroll 8
        for (int c = 0; c < 64; c++) {
            float4 w4 = *(const float4*)&Ws[c*64 + tx*4];
            float a0 = As[(ty*4+0)*68 + c];
            float a1 = As[(ty*4+1)*68 + c];
            float a2 = As[(ty*4+2)*68 + c];
            float a3 = As[(ty*4+3)*68 + c];
            acc[0][0] += a0*w4.x; acc[0][1] += a0*w4.y; acc[0][2] += a0*w4.z; acc[0][3] += a0*w4.w;
            acc[1][0] += a1*w4.x; acc[1][1] += a1*w4.y; acc[1][2] += a1*w4.z; acc[1][3] += a1*w4.w;
            acc[2][0] += a2*w4.x; acc[2][1] += a2*w4.y; acc[2][2] += a2*w4.z; acc[2][3] += a2*w4.w;
            acc[3][0] += a3*w4.x; acc[3][1] += a3*w4.y; acc[3][2] += a3*w4.z; acc[3][3] += a3*w4.w;
        }
    }
    float4 b4 = *(const float4*)&bias[col0 + tx*4];
    #pragma unroll
    for (int u = 0; u < 4; u++) {
        int r = row0 + ty*4 + u;
        if (r < M_UP) {
            *(float4*)&g_h[(size_t)r*448 + col0 + tx*4] =
                make_float4(acc[u][0]+b4.x, acc[u][1]+b4.y,
                            acc[u][2]+b4.z, acc[u][3]+b4.w);
        }
    }
}

// ---------------------------------------------------------------------------
// Build x_cat[b, i, 0:64]  = top/down-gathered h_flat (h viewed [B, Nr*7, 64])
//       x_cat[b, i, 64:128]= x2[b, i, :]
// one thread per float4 of x_cat; row = 32 float4
// ---------------------------------------------------------------------------
__global__ __launch_bounds__(256) void build_xcat_kernel(
    const float* __restrict__ x2, const int* __restrict__ topi,
    const int* __restrict__ downi)
{
    size_t idx = (size_t)blockIdx.x * 256 + threadIdx.x;
    const size_t total = (size_t)M_CONV * 32;
    if (idx >= total) return;
    int q = (int)(idx & 31);
    size_t bi = idx >> 5;                 // b*NH + i
    int b = (int)(bi / NHH);
    int i = (int)(bi - (size_t)b * NHH);
    const float* hf = g_h + (size_t)b * NR * 448;  // flat [Nr*7, 64]
    float4 v;
    if (q < 16) {
        if (i < NR) {
            int t = topi[i];
            v = ((const float4*)(hf + (size_t)t*64))[q];
        } else {
            int jj = i - NR;
            int d0 = downi[jj*2 + 0];
            int d1 = downi[jj*2 + 1];
            float4 a = ((const float4*)(hf + (size_t)d0*64))[q];
            float4 c = ((const float4*)(hf + (size_t)d1*64))[q];
            v = make_float4(0.5f*(a.x+c.x), 0.5f*(a.y+c.y),
                            0.5f*(a.z+c.z), 0.5f*(a.w+c.w));
        }
    } else {
        v = ((const float4*)x2)[bi*16 + (q - 16)];
    }
    ((float4*)g_xcat)[idx] = v;
}

// ---------------------------------------------------------------------------
// Fused gather conv GEMM: out[r, o] = sum_j sum_c x[nb(r,j), c] * W[j*C+c, o] + b[o]
// C = channels per neighbor (128 conv1, 64 conv2), K split in 64-wide sub-chunks.
// APPLY_BN: transform gathered values with bn1+lrelu on the fly (conv2 path).
// ---------------------------------------------------------------------------
template<int C, bool APPLY_BN>
__global__ __launch_bounds__(256) void conv_kernel(
    const float* __restrict__ x, const int* __restrict__ neigh,
    const float* __restrict__ W, const float* __restrict__ bias,
    float* __restrict__ out)
{
    __shared__ float As[64*68];
    __shared__ float Ws[64*64];
    __shared__ int   nidx[64];
    __shared__ float s_scale[64];
    __shared__ float s_shift[64];
    const int tid = threadIdx.x;
    const int tx = tid & 15, ty = tid >> 4;
    const int row0 = blockIdx.x * 64;

    if (APPLY_BN) {
        if (tid < 64)       s_scale[tid]    = g_bn[tid];
        else if (tid < 128) s_shift[tid-64] = g_bn[tid];
    }
    constexpr int NSUB = C / 64;
    float acc[4][4] = {};

    for (int jc = 0; jc < 7*NSUB; jc++) {
        const int j    = jc / NSUB;
        const int half = jc % NSUB;
        __syncthreads();                      // protect As/Ws reuse + s_scale visibility
        if (tid < 64) {
            int r = row0 + tid; if (r >= M_CONV) r = M_CONV - 1;
            int b = r / NHH;
            int n = r - b * NHH;
            nidx[tid] = b * NHH + neigh[n*7 + j];
        }
        __syncthreads();
        // gather A sub-tile: 64 rows x 64 channels
        for (int idx = tid; idx < 64*16; idx += 256) {
            int r = idx >> 4, q = idx & 15;
            float4 v = *(const float4*)&x[(size_t)nidx[r]*C + half*64 + q*4];
            if (APPLY_BN) {
                int c = q*4;
                v.x = v.x*s_scale[c+0] + s_shift[c+0]; v.x = fmaxf(v.x, 0.2f*v.x);
                v.y = v.y*s_scale[c+1] + s_shift[c+1]; v.y = fmaxf(v.y, 0.2f*v.y);
                v.z = v.z*s_scale[c+2] + s_shift[c+2]; v.z = fmaxf(v.z, 0.2f*v.z);
                v.w = v.w*s_scale[c+3] + s_shift[c+3]; v.w = fmaxf(v.w, 0.2f*v.w);
            }
            *(float4*)&As[r*68 + q*4] = v;
        }
        // W sub-tile: rows [j*C + half*64, +64), 64 cols
        for (int idx = tid; idx < 64*16; idx += 256) {
            int c = idx >> 4, q = idx & 15;
            *(float4*)&Ws[c*64 + q*4] =
                *(const float4*)&W[(size_t)(j*C + half*64 + c)*64 + q*4];
        }
        __syncthreads();
        #pragma unroll 8
        for (int c = 0; c < 64; c++) {
            float4 w4 = *(const float4*)&Ws[c*64 + tx*4];
            float a0 = As[(ty*4+0)*68 + c];
            float a1 = As[(ty*4+1)*68 + c];
            float a2 = As[(ty*4+2)*68 + c];
            float a3 = As[(ty*4+3)*68 + c];
            acc[0][0] += a0*w4.x; acc[0][1] += a0*w4.y; acc[0][2] += a0*w4.z; acc[0][3] += a0*w4.w;
            acc[1][0] += a1*w4.x; acc[1][1] += a1*w4.y; acc[1][2] += a1*w4.z; acc[1][3] += a1*w4.w;
            acc[2][0] += a2*w4.x; acc[2][1] += a2*w4.y; acc[2][2] += a2*w4.z; acc[2][3] += a2*w4.w;
            acc[3][0] += a3*w4.x; acc[3][1] += a3*w4.y; acc[3][2] += a3*w4.z; acc[3][3] += a3*w4.w;
        }
    }
    float4 b4 = *(const float4*)&bias[tx*4];
    #pragma unroll
    for (int u = 0; u < 4; u++) {
        int r = row0 + ty*4 + u;
        if (r < M_CONV) {
            *(float4*)&out[(size_t)r*64 + tx*4] =
                make_float4(acc[u][0]+b4.x, acc[u][1]+b4.y,
                            acc[u][2]+b4.z, acc[u][3]+b4.w);
        }
    }
}

// ---------------------------------------------------------------------------
// Deterministic per-channel BN statistics (two-level, fixed order)
// ---------------------------------------------------------------------------
__global__ __launch_bounds__(256) void stats_partial_kernel(const float* __restrict__ y)
{
    const int c   = threadIdx.x & 63;
    const int sub = threadIdx.x >> 6;
    float s = 0.f, ss = 0.f;
    for (int r = blockIdx.x*4 + sub; r < M_CONV; r += NPART*4) {
        float v = y[(size_t)r*64 + c];
        s += v; ss += v*v;
    }
    __shared__ float sh[512];
    sh[threadIdx.x]       = s;
    sh[256 + threadIdx.x] = ss;
    __syncthreads();
    if (threadIdx.x < 64) {
        float a = sh[c] + sh[64+c] + sh[128+c] + sh[192+c];
        float b = sh[256+c] + sh[320+c] + sh[384+c] + sh[448+c];
        g_part[blockIdx.x*128 + c]      = a;
        g_part[blockIdx.x*128 + 64 + c] = b;
    }
}

__global__ void stats_final_kernel(const float* __restrict__ gamma,
                                   const float* __restrict__ beta)
{
    int c = threadIdx.x;
    if (c >= 64) return;
    float s = 0.f, ss = 0.f;
    for (int p = 0; p < NPART; p++) {
        s  += g_part[p*128 + c];
        ss += g_part[p*128 + 64 + c];
    }
    const float inv = 1.0f / (float)M_CONV;
    float mean = s * inv;
    float var  = fmaxf(ss * inv - mean*mean, 0.f);
    float sc   = gamma[c] * rsqrtf(var + 1e-5f);
    g_bn[c]      = sc;
    g_bn[64 + c] = beta[c] - mean * sc;
}

// Final in-place BN + leaky relu on d_out
__global__ __launch_bounds__(256) void bn_act_kernel(float* __restrict__ y)
{
    size_t idx = (size_t)blockIdx.x * 256 + threadIdx.x;
    const size_t total = (size_t)M_CONV * 16;
    if (idx >= total) return;
    int c = ((int)idx & 15) * 4;
    float4 v = ((float4*)y)[idx];
    v.x = v.x*g_bn[c+0] + g_bn[64+c+0]; v.x = fmaxf(v.x, 0.2f*v.x);
    v.y = v.y*g_bn[c+1] + g_bn[64+c+1]; v.y = fmaxf(v.y, 0.2f*v.y);
    v.z = v.z*g_bn[c+2] + g_bn[64+c+2]; v.z = fmaxf(v.z, 0.2f*v.z);
    v.w = v.w*g_bn[c+3] + g_bn[64+c+3]; v.w = fmaxf(v.w, 0.2f*v.w);
    ((float4*)y)[idx] = v;
}

// ---------------------------------------------------------------------------
extern "C" void kernel_launch(void* const* d_in, const int* in_sizes, int n_in,
                              void* d_out, int out_size)
{
    const float* x1    = (const float*)d_in[0];
    const float* x2    = (const float*)d_in[1];
    const int*   neigh = (const int*)  d_in[2];
    const int*   topi  = (const int*)  d_in[3];
    const int*   downi = (const int*)  d_in[4];
    const float* up_W  = (const float*)d_in[5];
    const float* up_b  = (const float*)d_in[6];
    const float* w1    = (const float*)d_in[7];
    const float* b1    = (const float*)d_in[8];
    const float* g1    = (const float*)d_in[9];
    const float* be1   = (const float*)d_in[10];
    const float* w2    = (const float*)d_in[11];
    const float* b2    = (const float*)d_in[12];
    const float* g2    = (const float*)d_in[13];
    const float* be2   = (const float*)d_in[14];
    float* out = (float*)d_out;

    void *xcatp = nullptr, *y1p = nullptr;
    cudaGetSymbolAddress(&xcatp, g_xcat);
    cudaGetSymbolAddress(&y1p, g_y1);

    // 1) up GEMM
    gemm_up_kernel<<<dim3((M_UP + 63)/64, 7), 256>>>(x1, up_W, up_b);
    // 2) upconv gather + channel concat
    build_xcat_kernel<<<(int)(((size_t)M_CONV*32 + 255)/256), 256>>>(x2, topi, downi);
    // 3) conv1 (gather GEMM, K=896) -> g_y1 (pre-BN)
    conv_kernel<128, false><<<(M_CONV + 63)/64, 256>>>(
        (const float*)xcatp, neigh, w1, b1, (float*)y1p);
    // 4) bn1 stats
    stats_partial_kernel<<<NPART, 256>>>((const float*)y1p);
    stats_final_kernel<<<1, 64>>>(g1, be1);
    // 5) conv2 (gather GEMM, K=448, bn1+lrelu applied on the fly) -> d_out (pre-BN)
    conv_kernel<64, true><<<(M_CONV + 63)/64, 256>>>(
        (const float*)y1p, neigh, w2, b2, out);
    // 6) bn2 stats
    stats_partial_kernel<<<NPART, 256>>>((const float*)out);
    stats_final_kernel<<<1, 64>>>(g2, be2);
    // 7) final bn2 + lrelu in place
    bn_act_kernel<<<(int)(((size_t)M_CONV*16 + 255)/256), 256>>>(out);
}

// round 6
// speedup vs baseline: 2.1398x; 2.1398x over previous
#include <cuda_runtime.h>
#include <cuda_bf16.h>
#include <cstdint>

// Problem constants: B=2, Nr=40962, Nh=4*Nr-6=163842, Cin=128, Co=64
#define BB      2
#define NR      40962
#define NHH     163842
#define M_UP    (BB*NR)        // 81924
#define M_CONV  (BB*NHH)       // 327684
#define NPART   256

// ---------------------------------------------------------------------------
// Scratch (device globals; allocation-guard safe)
// Packed hi|lo bf16 rows: row of C channels occupies 2C bf16 (hi[0..C), lo[C..2C))
// ---------------------------------------------------------------------------
__device__ __nv_bfloat16 g_x1c[(size_t)M_UP * 256];     // x1 split   [M_UP][2*128]
__device__ float         g_h  [(size_t)M_UP * 448];     // up output  fp32
__device__ __nv_bfloat16 g_xcc[(size_t)M_CONV * 256];   // xcat split [M_CONV][2*128]
__device__ float         g_y1 [(size_t)M_CONV * 64];    // conv1 out  fp32 (pre-BN)
__device__ __nv_bfloat16 g_y2c[(size_t)M_CONV * 128];   // bn1(y1) split [M_CONV][2*64]
__device__ __nv_bfloat16 g_wuc[448 * 256];              // up_W^T  split [448][2*128]
__device__ __nv_bfloat16 g_w1c[64 * 1792];              // w1^T    split [64][2*896]
__device__ __nv_bfloat16 g_w2c[64 * 896];               // w2^T    split [64][2*448]
__device__ float         g_part[NPART * 128];
__device__ float         g_bn[128];                     // scale[64], shift[64]

// ---------------------------------------------------------------------------
// Helpers
// ---------------------------------------------------------------------------
__device__ __forceinline__ uint32_t su32(const void* p) {
    uint32_t a;
    asm("{ .reg .u64 t; cvta.to.shared.u64 t, %1; cvt.u32.u64 %0, t; }"
        : "=r"(a) : "l"(p));
    return a;
}

#define LDSM4(r0, r1, r2, r3, addr) \
    asm volatile("ldmatrix.sync.aligned.m8n8.x4.shared.b16 {%0,%1,%2,%3}, [%4];" \
                 : "=r"(r0), "=r"(r1), "=r"(r2), "=r"(r3) : "r"(addr))
#define LDSM2(r0, r1, addr) \
    asm volatile("ldmatrix.sync.aligned.m8n8.x2.shared.b16 {%0,%1}, [%2];" \
                 : "=r"(r0), "=r"(r1) : "r"(addr))

__device__ __forceinline__ void mma_bf16(float* d, const uint32_t* a, const uint32_t* b) {
    asm volatile(
        "mma.sync.aligned.m16n8k16.row.col.f32.bf16.bf16.f32 "
        "{%0,%1,%2,%3}, {%4,%5,%6,%7}, {%8,%9}, {%0,%1,%2,%3};"
        : "+f"(d[0]), "+f"(d[1]), "+f"(d[2]), "+f"(d[3])
        : "r"(a[0]), "r"(a[1]), "r"(a[2]), "r"(a[3]), "r"(b[0]), "r"(b[1]));
}

__device__ __forceinline__ void splitf(float v, float& hi, float& lo) {
    hi = __bfloat162float(__float2bfloat16(v));   // rn
    lo = v - hi;                                  // exact in fp32
}
__device__ __forceinline__ uint32_t pack2(float a, float b) {
    __nv_bfloat162 t;
    t.x = __float2bfloat16(a);
    t.y = __float2bfloat16(b);
    return *reinterpret_cast<uint32_t*>(&t);
}
__device__ __forceinline__ void split4(float4 v, uint2& h, uint2& l) {
    float h0,l0,h1,l1,h2,l2,h3,l3;
    splitf(v.x,h0,l0); splitf(v.y,h1,l1); splitf(v.z,h2,l2); splitf(v.w,h3,l3);
    h = make_uint2(pack2(h0,h1), pack2(h2,h3));
    l = make_uint2(pack2(l0,l1), pack2(l2,l3));
}

// ---------------------------------------------------------------------------
// mma.sync gather-GEMM (bf16x3 emulated fp32): out = X(gathered) @ W^T + bias
// src rows packed [hi(C)|lo(C)] bf16; wt rows packed [hi(Kt)|lo(Kt)], Kt = NJ*C.
// CTA: 128 rows x 64 cols; 8 warps as 4(row) x 2(col) of 32x32 warp tiles.
// K streamed in 64-wide chunks; per chunk: A1B1 + A2B1 (phase 1), A1B2 (phase 2).
// SMEM xor-swizzled for conflict-free ldmatrix.
// ---------------------------------------------------------------------------
template<int C, int NJ, bool GATHER>
__global__ __launch_bounds__(256) void mma_gemm(
    const __nv_bfloat16* __restrict__ src,
    const __nv_bfloat16* __restrict__ wt,
    const int* __restrict__ neigh,
    const float* __restrict__ bias,
    float* __restrict__ out, int M, int ostride)
{
    constexpr int Kt = NJ * C;
    constexpr int NH = C / 64;
    __shared__ __align__(16) __nv_bfloat16 sAh[128 * 64];
    __shared__ __align__(16) __nv_bfloat16 sAl[128 * 64];
    __shared__ __align__(16) __nv_bfloat16 sB [64 * 64];

    const int tid  = threadIdx.x;
    const int lane = tid & 31;
    const int wid  = tid >> 5;
    const int row0 = blockIdx.x * 128;
    const int col0 = blockIdx.y * 64;
    const int warp_r = wid & 3;     // 32-row tile
    const int warp_c = wid >> 2;    // 32-col tile

    const uint32_t baseAh = su32(sAh);
    const uint32_t baseAl = su32(sAl);
    const uint32_t baseB  = su32(sB);

    // loader mapping: 8 threads per row, 16B each
    const int lr = tid >> 3;        // 0..31
    const int q  = tid & 7;         // 16B unit

    float acc[2][4][4];
    #pragma unroll
    for (int a = 0; a < 2; a++)
        #pragma unroll
        for (int b = 0; b < 4; b++)
            #pragma unroll
            for (int c = 0; c < 4; c++) acc[a][b][c] = 0.f;

    // precomputed ldmatrix lane geometry
    const int a_row_in = ((lane >> 3) & 1) * 8 + (lane & 7);   // + mtile*16 + warp_r*32
    const int a_kseg   = (lane >> 4);                          // 0/1 -> k +0/+8
    const int b_row_in = (lane & 7);
    const int b_kseg   = ((lane >> 3) & 1);

    for (int j = 0; j < NJ; j++) {
        size_t abase[4];
        #pragma unroll
        for (int i = 0; i < 4; i++) {
            int r = row0 + lr + 32 * i; if (r >= M) r = M - 1;
            int nid;
            if (GATHER) {
                int b = (r >= NHH) ? 1 : 0;
                int n = r - b * NHH;
                nid = b * NHH + neigh[n * 7 + j];
            } else nid = r;
            abase[i] = (size_t)nid * (2 * C);
        }
        for (int h = 0; h < NH; h++) {
            const int koff = h * 64;
            __syncthreads();    // previous chunk's phase-2 reads done
            // ---- load A hi + lo (gathered), swizzled ----
            #pragma unroll
            for (int i = 0; i < 4; i++) {
                int rr = lr + 32 * i;
                int u  = q ^ (rr & 7);
                int doff = rr * 64 + u * 8;
                *(uint4*)&sAh[doff] = *(const uint4*)(src + abase[i] + koff + q * 8);
                *(uint4*)&sAl[doff] = *(const uint4*)(src + abase[i] + C + koff + q * 8);
            }
            // ---- load B hi ----
            #pragma unroll
            for (int t = 0; t < 2; t++) {
                int n = lr + 32 * t;
                int u = q ^ (n & 7);
                *(uint4*)&sB[n * 64 + u * 8] =
                    *(const uint4*)(wt + (size_t)(col0 + n) * (2 * Kt)
                                       + (size_t)j * C + koff + q * 8);
            }
            __syncthreads();
            // ---- phase 1: A1*B1 + A2*B1 ----
            #pragma unroll
            for (int k16 = 0; k16 < 4; k16++) {
                const int k0 = k16 * 16;
                uint32_t ah[2][4], al[2][4], bf[4][2];
                #pragma unroll
                for (int mt = 0; mt < 2; mt++) {
                    int arow = warp_r * 32 + mt * 16 + a_row_in;
                    int aku  = (k0 >> 3) + a_kseg;
                    uint32_t off = (uint32_t)(arow * 64 + (aku ^ (arow & 7)) * 8) * 2;
                    LDSM4(ah[mt][0], ah[mt][1], ah[mt][2], ah[mt][3], baseAh + off);
                    LDSM4(al[mt][0], al[mt][1], al[mt][2], al[mt][3], baseAl + off);
                }
                #pragma unroll
                for (int nt = 0; nt < 4; nt++) {
                    int brow = warp_c * 32 + nt * 8 + b_row_in;
                    int bku  = (k0 >> 3) + b_kseg;
                    uint32_t off = (uint32_t)(brow * 64 + (bku ^ (brow & 7)) * 8) * 2;
                    LDSM2(bf[nt][0], bf[nt][1], baseB + off);
                }
                #pragma unroll
                for (int mt = 0; mt < 2; mt++)
                    #pragma unroll
                    for (int nt = 0; nt < 4; nt++) {
                        mma_bf16(acc[mt][nt], ah[mt], bf[nt]);
                        mma_bf16(acc[mt][nt], al[mt], bf[nt]);
                    }
            }
            __syncthreads();
            // ---- load B lo ----
            #pragma unroll
            for (int t = 0; t < 2; t++) {
                int n = lr + 32 * t;
                int u = q ^ (n & 7);
                *(uint4*)&sB[n * 64 + u * 8] =
                    *(const uint4*)(wt + (size_t)(col0 + n) * (2 * Kt)
                                       + Kt + (size_t)j * C + koff + q * 8);
            }
            __syncthreads();
            // ---- phase 2: A1*B2 ----
            #pragma unroll
            for (int k16 = 0; k16 < 4; k16++) {
                const int k0 = k16 * 16;
                uint32_t ah[2][4], bf[4][2];
                #pragma unroll
                for (int mt = 0; mt < 2; mt++) {
                    int arow = warp_r * 32 + mt * 16 + a_row_in;
                    int aku  = (k0 >> 3) + a_kseg;
                    uint32_t off = (uint32_t)(arow * 64 + (aku ^ (arow & 7)) * 8) * 2;
                    LDSM4(ah[mt][0], ah[mt][1], ah[mt][2], ah[mt][3], baseAh + off);
                }
                #pragma unroll
                for (int nt = 0; nt < 4; nt++) {
                    int brow = warp_c * 32 + nt * 8 + b_row_in;
                    int bku  = (k0 >> 3) + b_kseg;
                    uint32_t off = (uint32_t)(brow * 64 + (bku ^ (brow & 7)) * 8) * 2;
                    LDSM2(bf[nt][0], bf[nt][1], baseB + off);
                }
                #pragma unroll
                for (int mt = 0; mt < 2; mt++)
                    #pragma unroll
                    for (int nt = 0; nt < 4; nt++)
                        mma_bf16(acc[mt][nt], ah[mt], bf[nt]);
            }
        }
    }

    // ---- epilogue: direct fp32 stores + bias ----
    #pragma unroll
    for (int mt = 0; mt < 2; mt++) {
        #pragma unroll
        for (int nt = 0; nt < 4; nt++) {
            int r  = row0 + warp_r * 32 + mt * 16 + (lane >> 2);
            int cc = col0 + warp_c * 32 + nt * 8 + (lane & 3) * 2;
            float bx = bias[cc], by = bias[cc + 1];
            if (r < M)
                *(float2*)&out[(size_t)r * ostride + cc] =
                    make_float2(acc[mt][nt][0] + bx, acc[mt][nt][1] + by);
            if (r + 8 < M)
                *(float2*)&out[(size_t)(r + 8) * ostride + cc] =
                    make_float2(acc[mt][nt][2] + bx, acc[mt][nt][3] + by);
        }
    }
}

// ---------------------------------------------------------------------------
// Prep kernels
// ---------------------------------------------------------------------------
// Transpose + hi/lo split: src fp32 [K][N] -> dst bf16 [N][2K]
__global__ void tspl_kernel(const float* __restrict__ src,
                            __nv_bfloat16* __restrict__ dst, int K, int N)
{
    int idx = blockIdx.x * 256 + threadIdx.x;
    if (idx >= K * N) return;
    int k = idx / N, n = idx - k * N;
    float hi, lo; splitf(src[idx], hi, lo);
    dst[(size_t)n * 2 * K + k]     = __float2bfloat16(hi);
    dst[(size_t)n * 2 * K + K + k] = __float2bfloat16(lo);
}

// x1 fp32 [M_UP][128] -> g_x1c [M_UP][2*128]
__global__ __launch_bounds__(256) void x1split_kernel(const float* __restrict__ x1)
{
    size_t idx = (size_t)blockIdx.x * 256 + threadIdx.x;
    if (idx >= (size_t)M_UP * 32) return;
    size_t r = idx >> 5; int q = (int)(idx & 31);
    float4 v = *(const float4*)(x1 + r * 128 + q * 4);
    uint2 h, l; split4(v, h, l);
    ((uint2*)g_x1c)[r * 64 + q]      = h;
    ((uint2*)g_x1c)[r * 64 + 32 + q] = l;
}

// upconv gather + concat, split to hi/lo: g_xcc [M_CONV][2*128]
__global__ __launch_bounds__(256) void build_xcat_kernel(
    const float* __restrict__ x2, const int* __restrict__ topi,
    const int* __restrict__ downi)
{
    size_t idx = (size_t)blockIdx.x * 256 + threadIdx.x;
    if (idx >= (size_t)M_CONV * 32) return;
    int q = (int)(idx & 31);
    size_t bi = idx >> 5;
    int b = (bi >= NHH) ? 1 : 0;
    int i = (int)(bi - (size_t)b * NHH);
    const float* hf = g_h + (size_t)b * NR * 448;   // flat [Nr*7][64]
    float4 v;
    if (q < 16) {
        if (i < NR) {
            int t = topi[i];
            v = ((const float4*)(hf + (size_t)t * 64))[q];
        } else {
            int jj = i - NR;
            int d0 = downi[jj * 2 + 0];
            int d1 = downi[jj * 2 + 1];
            float4 a = ((const float4*)(hf + (size_t)d0 * 64))[q];
            float4 c = ((const float4*)(hf + (size_t)d1 * 64))[q];
            v = make_float4(0.5f*(a.x+c.x), 0.5f*(a.y+c.y),
                            0.5f*(a.z+c.z), 0.5f*(a.w+c.w));
        }
    } else {
        v = ((const float4*)x2)[bi * 16 + (q - 16)];
    }
    uint2 h, l; split4(v, h, l);
    ((uint2*)g_xcc)[bi * 64 + q]      = h;
    ((uint2*)g_xcc)[bi * 64 + 32 + q] = l;
}

// bn1 + lrelu applied to g_y1, split -> g_y2c [M_CONV][2*64]
__global__ __launch_bounds__(256) void bn_split_kernel()
{
    size_t idx = (size_t)blockIdx.x * 256 + threadIdx.x;
    if (idx >= (size_t)M_CONV * 16) return;
    size_t r = idx >> 4; int q = (int)(idx & 15);
    int c = q * 4;
    float4 v = *(const float4*)(g_y1 + r * 64 + c);
    v.x = v.x * g_bn[c+0] + g_bn[64+c+0]; v.x = fmaxf(v.x, 0.2f * v.x);
    v.y = v.y * g_bn[c+1] + g_bn[64+c+1]; v.y = fmaxf(v.y, 0.2f * v.y);
    v.z = v.z * g_bn[c+2] + g_bn[64+c+2]; v.z = fmaxf(v.z, 0.2f * v.z);
    v.w = v.w * g_bn[c+3] + g_bn[64+c+3]; v.w = fmaxf(v.w, 0.2f * v.w);
    uint2 h, l; split4(v, h, l);
    ((uint2*)g_y2c)[r * 32 + q]      = h;
    ((uint2*)g_y2c)[r * 32 + 16 + q] = l;
}

// ---------------------------------------------------------------------------
// Deterministic BN statistics (two-level, fixed order)
// ---------------------------------------------------------------------------
__global__ __launch_bounds__(256) void stats_partial_kernel(const float* __restrict__ y)
{
    const int c   = threadIdx.x & 63;
    const int sub = threadIdx.x >> 6;
    float s = 0.f, ss = 0.f;
    for (int r = blockIdx.x * 4 + sub; r < M_CONV; r += NPART * 4) {
        float v = y[(size_t)r * 64 + c];
        s += v; ss += v * v;
    }
    __shared__ float sh[512];
    sh[threadIdx.x]       = s;
    sh[256 + threadIdx.x] = ss;
    __syncthreads();
    if (threadIdx.x < 64) {
        float a = sh[c] + sh[64+c] + sh[128+c] + sh[192+c];
        float b = sh[256+c] + sh[320+c] + sh[384+c] + sh[448+c];
        g_part[blockIdx.x * 128 + c]      = a;
        g_part[blockIdx.x * 128 + 64 + c] = b;
    }
}

__global__ void stats_final_kernel(const float* __restrict__ gamma,
                                   const float* __restrict__ beta)
{
    int c = threadIdx.x;
    if (c >= 64) return;
    float s = 0.f, ss = 0.f;
    for (int p = 0; p < NPART; p++) {
        s  += g_part[p * 128 + c];
        ss += g_part[p * 128 + 64 + c];
    }
    const float inv = 1.0f / (float)M_CONV;
    float mean = s * inv;
    float var  = fmaxf(ss * inv - mean * mean, 0.f);
    float sc   = gamma[c] * rsqrtf(var + 1e-5f);
    g_bn[c]      = sc;
    g_bn[64 + c] = beta[c] - mean * sc;
}

// Final in-place bn2 + lrelu on d_out
__global__ __launch_bounds__(256) void bn_act_kernel(float* __restrict__ y)
{
    size_t idx = (size_t)blockIdx.x * 256 + threadIdx.x;
    if (idx >= (size_t)M_CONV * 16) return;
    int c = ((int)idx & 15) * 4;
    float4 v = ((float4*)y)[idx];
    v.x = v.x * g_bn[c+0] + g_bn[64+c+0]; v.x = fmaxf(v.x, 0.2f * v.x);
    v.y = v.y * g_bn[c+1] + g_bn[64+c+1]; v.y = fmaxf(v.y, 0.2f * v.y);
    v.z = v.z * g_bn[c+2] + g_bn[64+c+2]; v.z = fmaxf(v.z, 0.2f * v.z);
    v.w = v.w * g_bn[c+3] + g_bn[64+c+3]; v.w = fmaxf(v.w, 0.2f * v.w);
    ((float4*)y)[idx] = v;
}

// ---------------------------------------------------------------------------
extern "C" void kernel_launch(void* const* d_in, const int* in_sizes, int n_in,
                              void* d_out, int out_size)
{
    const float* x1    = (const float*)d_in[0];
    const float* x2    = (const float*)d_in[1];
    const int*   neigh = (const int*)  d_in[2];
    const int*   topi  = (const int*)  d_in[3];
    const int*   downi = (const int*)  d_in[4];
    const float* up_W  = (const float*)d_in[5];
    const float* up_b  = (const float*)d_in[6];
    const float* w1    = (const float*)d_in[7];
    const float* b1    = (const float*)d_in[8];
    const float* g1    = (const float*)d_in[9];
    const float* be1   = (const float*)d_in[10];
    const float* w2    = (const float*)d_in[11];
    const float* b2    = (const float*)d_in[12];
    const float* g2    = (const float*)d_in[13];
    const float* be2   = (const float*)d_in[14];
    float* out = (float*)d_out;

    void *p_x1c, *p_h, *p_xcc, *p_y1, *p_y2c, *p_wuc, *p_w1c, *p_w2c;
    cudaGetSymbolAddress(&p_x1c, g_x1c);
    cudaGetSymbolAddress(&p_h,   g_h);
    cudaGetSymbolAddress(&p_xcc, g_xcc);
    cudaGetSymbolAddress(&p_y1,  g_y1);
    cudaGetSymbolAddress(&p_y2c, g_y2c);
    cudaGetSymbolAddress(&p_wuc, g_wuc);
    cudaGetSymbolAddress(&p_w1c, g_w1c);
    cudaGetSymbolAddress(&p_w2c, g_w2c);

    // 0) weight transpose+split, x1 split
    tspl_kernel<<<(128*448 + 255)/256, 256>>>(up_W, (__nv_bfloat16*)p_wuc, 128, 448);
    tspl_kernel<<<(896*64  + 255)/256, 256>>>(w1,   (__nv_bfloat16*)p_w1c, 896, 64);
    tspl_kernel<<<(448*64  + 255)/256, 256>>>(w2,   (__nv_bfloat16*)p_w2c, 448, 64);
    x1split_kernel<<<(int)(((size_t)M_UP*32 + 255)/256), 256>>>(x1);

    // 1) up GEMM: [M_UP x 448] = x1 @ up_W + up_b
    mma_gemm<128, 1, false><<<dim3((M_UP + 127)/128, 7), 256>>>(
        (const __nv_bfloat16*)p_x1c, (const __nv_bfloat16*)p_wuc,
        nullptr, up_b, (float*)p_h, M_UP, 448);

    // 2) upconv gather + concat + split
    build_xcat_kernel<<<(int)(((size_t)M_CONV*32 + 255)/256), 256>>>(x2, topi, downi);

    // 3) conv1 (gather GEMM, K=896) -> g_y1 (pre-BN)
    mma_gemm<128, 7, true><<<dim3((M_CONV + 127)/128, 1), 256>>>(
        (const __nv_bfloat16*)p_xcc, (const __nv_bfloat16*)p_w1c,
        neigh, b1, (float*)p_y1, M_CONV, 64);

    // 4) bn1 stats + split input for conv2
    stats_partial_kernel<<<NPART, 256>>>((const float*)p_y1);
    stats_final_kernel<<<1, 64>>>(g1, be1);
    bn_split_kernel<<<(int)(((size_t)M_CONV*16 + 255)/256), 256>>>();

    // 5) conv2 (gather GEMM, K=448) -> d_out (pre-BN)
    mma_gemm<64, 7, true><<<dim3((M_CONV + 127)/128, 1), 256>>>(
        (const __nv_bfloat16*)p_y2c, (const __nv_bfloat16*)p_w2c,
        neigh, b2, out, M_CONV, 64);

    // 6) bn2 stats + final activation in place
    stats_partial_kernel<<<NPART, 256>>>(out);
    stats_final_kernel<<<1, 64>>>(g2, be2);
    bn_act_kernel<<<(int)(((size_t)M_CONV*16 + 255)/256), 256>>>(out);
}

// round 8
// speedup vs baseline: 2.8784x; 1.3451x over previous
#include <cuda_runtime.h>
#include <cuda_bf16.h>
#include <cstdint>

// Problem constants: B=2, Nr=40962, Nh=4*Nr-6=163842, Cin=128, Co=64
#define BB      2
#define NR      40962
#define NHH     163842
#define M_UP    (BB*NR)        // 81924
#define M_CONV  (BB*NHH)       // 327684
#define NCTA_CONV ((M_CONV + 127) / 128)   // 2561

// Dynamic smem: 2 stages x (Ah 16K | Al 16K | Bh 8K | Bl 8K) + 4K stats red
#define STG_BYTES 49152
#define SMEM_DYN  (2 * STG_BYTES + 4096)

// ---------------------------------------------------------------------------
// Scratch (device globals; allocation-guard safe)
// Packed hi|lo bf16 rows: row of C channels occupies 2C bf16 (hi[0..C), lo[C..2C))
// ---------------------------------------------------------------------------
__device__ __nv_bfloat16 g_x1c[(size_t)M_UP * 256];     // x1 split   [M_UP][2*128]
__device__ float         g_h  [(size_t)M_UP * 448];     // up output  fp32
__device__ __nv_bfloat16 g_xcc[(size_t)M_CONV * 256];   // xcat split [M_CONV][2*128]
__device__ float         g_y1 [(size_t)M_CONV * 64];    // conv1 out  fp32 (pre-BN)
__device__ __nv_bfloat16 g_y2c[(size_t)M_CONV * 128];   // bn1(y1) split [M_CONV][2*64]
__device__ __nv_bfloat16 g_wuc[448 * 256];              // up_W^T  split [448][2*128]
__device__ __nv_bfloat16 g_w1c[64 * 1792];              // w1^T    split [64][2*896]
__device__ __nv_bfloat16 g_w2c[64 * 896];               // w2^T    split [64][2*448]
__device__ float         g_stat[(size_t)NCTA_CONV * 128]; // per-CTA col sums (s|ss)
__device__ float         g_part[128 * 128];             // stage-2 partials
__device__ float         g_bn[128];                     // scale[64], shift[64]

// ---------------------------------------------------------------------------
// Helpers
// ---------------------------------------------------------------------------
__device__ __forceinline__ uint32_t su32(const void* p) {
    uint32_t a;
    asm("{ .reg .u64 t; cvta.to.shared.u64 t, %1; cvt.u32.u64 %0, t; }"
        : "=r"(a) : "l"(p));
    return a;
}

#define LDSM4(r0, r1, r2, r3, addr) \
    asm volatile("ldmatrix.sync.aligned.m8n8.x4.shared.b16 {%0,%1,%2,%3}, [%4];" \
                 : "=r"(r0), "=r"(r1), "=r"(r2), "=r"(r3) : "r"(addr))
#define LDSM2(r0, r1, addr) \
    asm volatile("ldmatrix.sync.aligned.m8n8.x2.shared.b16 {%0,%1}, [%2];" \
                 : "=r"(r0), "=r"(r1) : "r"(addr))
#define CP16(dst, srcp) \
    asm volatile("cp.async.cg.shared.global [%0], [%1], 16;" \
                 :: "r"(dst), "l"(srcp) : "memory")

__device__ __forceinline__ void mma_bf16(float* d, const uint32_t* a, const uint32_t* b) {
    asm volatile(
        "mma.sync.aligned.m16n8k16.row.col.f32.bf16.bf16.f32 "
        "{%0,%1,%2,%3}, {%4,%5,%6,%7}, {%8,%9}, {%0,%1,%2,%3};"
        : "+f"(d[0]), "+f"(d[1]), "+f"(d[2]), "+f"(d[3])
        : "r"(a[0]), "r"(a[1]), "r"(a[2]), "r"(a[3]), "r"(b[0]), "r"(b[1]));
}

__device__ __forceinline__ void splitf(float v, float& hi, float& lo) {
    hi = __bfloat162float(__float2bfloat16(v));   // rn
    lo = v - hi;                                  // exact in fp32
}
__device__ __forceinline__ uint32_t pack2(float a, float b) {
    __nv_bfloat162 t;
    t.x = __float2bfloat16(a);
    t.y = __float2bfloat16(b);
    return *reinterpret_cast<uint32_t*>(&t);
}
__device__ __forceinline__ void split4(float4 v, uint2& h, uint2& l) {
    float h0,l0,h1,l1,h2,l2,h3,l3;
    splitf(v.x,h0,l0); splitf(v.y,h1,l1); splitf(v.z,h2,l2); splitf(v.w,h3,l3);
    h = make_uint2(pack2(h0,h1), pack2(h2,h3));
    l = make_uint2(pack2(l0,l1), pack2(l2,l3));
}

// ---------------------------------------------------------------------------
// Pipelined mma.sync gather-GEMM (bf16x3 emulated fp32): out = X @ W^T + bias
// src rows packed [hi(C)|lo(C)] bf16; wt rows packed [hi(Kt)|lo(Kt)], Kt = NJ*C.
// CTA: 128 rows x 64 cols; 8 warps = 4(row) x 2(col) of 32x32 warp tiles.
// K streamed in 64-chunks, cp.async double-buffered (2 stages); per k16:
// A1B1 + A2B1 + A1B2 (A2B2 dropped, ~2^-18 rel).
// STATS: per-CTA deterministic column sum/sumsq written to g_stat.
// ---------------------------------------------------------------------------
template<int C, int NJ, bool GATHER, bool STATS>
__global__ __launch_bounds__(256) void mma_gemm(
    const __nv_bfloat16* __restrict__ src,
    const __nv_bfloat16* __restrict__ wt,
    const int* __restrict__ neigh,
    const float* __restrict__ bias,
    float* __restrict__ out, int M, int ostride)
{
    constexpr int Kt  = NJ * C;
    constexpr int NH  = C / 64;
    constexpr int NCH = NJ * NH;
    extern __shared__ __align__(16) char dsm[];
    const uint32_t dbase = su32(dsm);

    const int tid  = threadIdx.x;
    const int lane = tid & 31;
    const int wid  = tid >> 5;
    const int row0 = blockIdx.x * 128;
    const int col0 = blockIdx.y * 64;
    const int warp_r = wid & 3;
    const int warp_c = wid >> 2;

    const int lr = tid >> 3;        // 0..31 loader row
    const int q  = tid & 7;         // 16B unit

    float acc[2][4][4];
    #pragma unroll
    for (int a = 0; a < 2; a++)
        #pragma unroll
        for (int b = 0; b < 4; b++)
            #pragma unroll
            for (int c = 0; c < 4; c++) acc[a][b][c] = 0.f;

    const int a_row_in = ((lane >> 3) & 1) * 8 + (lane & 7);
    const int a_kseg   = (lane >> 4);
    const int b_row_in = (lane & 7);
    const int b_kseg   = ((lane >> 3) & 1);

    auto issue_load = [&](int c, int s) {
        const int j    = c / NH;
        const int koff = (c % NH) * 64;
        const uint32_t stg = dbase + (uint32_t)s * STG_BYTES;
        #pragma unroll
        for (int i = 0; i < 4; i++) {
            int r = row0 + lr + 32 * i; if (r >= M) r = M - 1;
            int nid;
            if (GATHER) {
                int b = (r >= NHH) ? 1 : 0;
                int n = r - b * NHH;
                nid = b * NHH + __ldg(&neigh[n * 7 + j]);
            } else nid = r;
            const __nv_bfloat16* sp = src + (size_t)nid * (2 * C) + koff + q * 8;
            int rr = lr + 32 * i;
            uint32_t doff = (uint32_t)((rr * 8 + (q ^ (rr & 7))) << 4);
            CP16(stg + doff, sp);                   // A hi
            CP16(stg + 16384 + doff, sp + C);       // A lo
        }
        #pragma unroll
        for (int t = 0; t < 2; t++) {
            int n = lr + 32 * t;
            const __nv_bfloat16* wp =
                wt + (size_t)(col0 + n) * (2 * Kt) + (size_t)j * C + koff + q * 8;
            uint32_t doff = (uint32_t)((n * 8 + (q ^ (n & 7))) << 4);
            CP16(stg + 32768 + doff, wp);           // B hi
            CP16(stg + 40960 + doff, wp + Kt);      // B lo
        }
        asm volatile("cp.async.commit_group;" ::: "memory");
    };

    issue_load(0, 0);
    for (int c = 0; c < NCH; c++) {
        if (c + 1 < NCH) {
            issue_load(c + 1, (c + 1) & 1);
            asm volatile("cp.async.wait_group 1;" ::: "memory");
        } else {
            asm volatile("cp.async.wait_group 0;" ::: "memory");
        }
        __syncthreads();
        const uint32_t stg = dbase + (uint32_t)(c & 1) * STG_BYTES;
        #pragma unroll
        for (int k16 = 0; k16 < 4; k16++) {
            const int kb = k16 * 2;
            uint32_t ah[2][4], al[2][4], bh[4][2], bl[4][2];
            #pragma unroll
            for (int mt = 0; mt < 2; mt++) {
                int arow = warp_r * 32 + mt * 16 + a_row_in;
                int aku  = kb + a_kseg;
                uint32_t off = (uint32_t)((arow * 8 + (aku ^ (arow & 7))) << 4);
                LDSM4(ah[mt][0], ah[mt][1], ah[mt][2], ah[mt][3], stg + off);
                LDSM4(al[mt][0], al[mt][1], al[mt][2], al[mt][3], stg + 16384 + off);
            }
            #pragma unroll
            for (int nt = 0; nt < 4; nt++) {
                int brow = warp_c * 32 + nt * 8 + b_row_in;
                int bku  = kb + b_kseg;
                uint32_t off = (uint32_t)((brow * 8 + (bku ^ (brow & 7))) << 4);
                LDSM2(bh[nt][0], bh[nt][1], stg + 32768 + off);
                LDSM2(bl[nt][0], bl[nt][1], stg + 40960 + off);
            }
            #pragma unroll
            for (int mt = 0; mt < 2; mt++)
                #pragma unroll
                for (int nt = 0; nt < 4; nt++) {
                    mma_bf16(acc[mt][nt], ah[mt], bh[nt]);
                    mma_bf16(acc[mt][nt], al[mt], bh[nt]);
                    mma_bf16(acc[mt][nt], ah[mt], bl[nt]);
                }
        }
        __syncthreads();
    }

    // ---- epilogue: fp32 stores + bias (+ per-CTA deterministic stats) ----
    float s_loc[8], ss_loc[8];
    if (STATS) {
        #pragma unroll
        for (int i = 0; i < 8; i++) { s_loc[i] = 0.f; ss_loc[i] = 0.f; }
    }
    #pragma unroll
    for (int mt = 0; mt < 2; mt++) {
        #pragma unroll
        for (int nt = 0; nt < 4; nt++) {
            int r  = row0 + warp_r * 32 + mt * 16 + (lane >> 2);
            int cc = col0 + warp_c * 32 + nt * 8 + (lane & 3) * 2;
            float bx = bias[cc], by = bias[cc + 1];
            float v0 = acc[mt][nt][0] + bx, v1 = acc[mt][nt][1] + by;
            float v2 = acc[mt][nt][2] + bx, v3 = acc[mt][nt][3] + by;
            if (r < M) {
                *(float2*)&out[(size_t)r * ostride + cc] = make_float2(v0, v1);
                if (STATS) {
                    s_loc[nt*2]   += v0; ss_loc[nt*2]   += v0 * v0;
                    s_loc[nt*2+1] += v1; ss_loc[nt*2+1] += v1 * v1;
                }
            }
            if (r + 8 < M) {
                *(float2*)&out[(size_t)(r + 8) * ostride + cc] = make_float2(v2, v3);
                if (STATS) {
                    s_loc[nt*2]   += v2; ss_loc[nt*2]   += v2 * v2;
                    s_loc[nt*2+1] += v3; ss_loc[nt*2+1] += v3 * v3;
                }
            }
        }
    }
    if (STATS) {
        // reduce over the 8 lane-groups holding different rows (fixed order)
        #pragma unroll
        for (int i = 0; i < 8; i++) {
            #pragma unroll
            for (int st = 4; st < 32; st <<= 1) {
                s_loc[i]  += __shfl_xor_sync(0xFFFFFFFFu, s_loc[i],  st);
                ss_loc[i] += __shfl_xor_sync(0xFFFFFFFFu, ss_loc[i], st);
            }
        }
        float* sred = (float*)(dsm + 2 * STG_BYTES);   // [8w][64c] s, then ss
        __syncthreads();
        if (lane < 4) {
            #pragma unroll
            for (int i = 0; i < 8; i++) {
                int colg = warp_c * 32 + (i >> 1) * 8 + lane * 2 + (i & 1);
                sred[wid * 64 + colg]       = s_loc[i];
                sred[512 + wid * 64 + colg] = ss_loc[i];
            }
        }
        __syncthreads();
        if (tid < 64) {
            int col = tid;
            int wb  = (col >= 32) ? 4 : 0;
            float s  = sred[(wb+0)*64+col] + sred[(wb+1)*64+col]
                     + sred[(wb+2)*64+col] + sred[(wb+3)*64+col];
            float ss = sred[512+(wb+0)*64+col] + sred[512+(wb+1)*64+col]
                     + sred[512+(wb+2)*64+col] + sred[512+(wb+3)*64+col];
            g_stat[(size_t)blockIdx.x * 128 + col]      = s;
            g_stat[(size_t)blockIdx.x * 128 + 64 + col] = ss;
        }
    }
}

// ---------------------------------------------------------------------------
// Prep kernels
// ---------------------------------------------------------------------------
__global__ void tspl_kernel(const float* __restrict__ src,
                            __nv_bfloat16* __restrict__ dst, int K, int N)
{
    int idx = blockIdx.x * 256 + threadIdx.x;
    if (idx >= K * N) return;
    int k = idx / N, n = idx - k * N;
    float hi, lo; splitf(src[idx], hi, lo);
    dst[(size_t)n * 2 * K + k]     = __float2bfloat16(hi);
    dst[(size_t)n * 2 * K + K + k] = __float2bfloat16(lo);
}

__global__ __launch_bounds__(256) void x1split_kernel(const float* __restrict__ x1)
{
    size_t idx = (size_t)blockIdx.x * 256 + threadIdx.x;
    if (idx >= (size_t)M_UP * 32) return;
    size_t r = idx >> 5; int q = (int)(idx & 31);
    float4 v = *(const float4*)(x1 + r * 128 + q * 4);
    uint2 h, l; split4(v, h, l);
    ((uint2*)g_x1c)[r * 64 + q]      = h;
    ((uint2*)g_x1c)[r * 64 + 32 + q] = l;
}

__global__ __launch_bounds__(256) void build_xcat_kernel(
    const float* __restrict__ x2, const int* __restrict__ topi,
    const int* __restrict__ downi)
{
    size_t idx = (size_t)blockIdx.x * 256 + threadIdx.x;
    if (idx >= (size_t)M_CONV * 32) return;
    int q = (int)(idx & 31);
    size_t bi = idx >> 5;
    int b = (bi >= NHH) ? 1 : 0;
    int i = (int)(bi - (size_t)b * NHH);
    const float* hf = g_h + (size_t)b * NR * 448;   // flat [Nr*7][64]
    float4 v;
    if (q < 16) {
        if (i < NR) {
            int t = topi[i];
            v = ((const float4*)(hf + (size_t)t * 64))[q];
        } else {
            int jj = i - NR;
            int d0 = downi[jj * 2 + 0];
            int d1 = downi[jj * 2 + 1];
            float4 a = ((const float4*)(hf + (size_t)d0 * 64))[q];
            float4 c = ((const float4*)(hf + (size_t)d1 * 64))[q];
            v = make_float4(0.5f*(a.x+c.x), 0.5f*(a.y+c.y),
                            0.5f*(a.z+c.z), 0.5f*(a.w+c.w));
        }
    } else {
        v = ((const float4*)x2)[bi * 16 + (q - 16)];
    }
    uint2 h, l; split4(v, h, l);
    ((uint2*)g_xcc)[bi * 64 + q]      = h;
    ((uint2*)g_xcc)[bi * 64 + 32 + q] = l;
}

// bn1 + lrelu applied to g_y1, split -> g_y2c [M_CONV][2*64]
__global__ __launch_bounds__(256) void bn_split_kernel()
{
    size_t idx = (size_t)blockIdx.x * 256 + threadIdx.x;
    if (idx >= (size_t)M_CONV * 16) return;
    size_t r = idx >> 4; int q = (int)(idx & 15);
    int c = q * 4;
    float4 v = *(const float4*)(g_y1 + r * 64 + c);
    v.x = v.x * g_bn[c+0] + g_bn[64+c+0]; v.x = fmaxf(v.x, 0.2f * v.x);
    v.y = v.y * g_bn[c+1] + g_bn[64+c+1]; v.y = fmaxf(v.y, 0.2f * v.y);
    v.z = v.z * g_bn[c+2] + g_bn[64+c+2]; v.z = fmaxf(v.z, 0.2f * v.z);
    v.w = v.w * g_bn[c+3] + g_bn[64+c+3]; v.w = fmaxf(v.w, 0.2f * v.w);
    uint2 h, l; split4(v, h, l);
    ((uint2*)g_y2c)[r * 32 + q]      = h;
    ((uint2*)g_y2c)[r * 32 + 16 + q] = l;
}

// ---------------------------------------------------------------------------
// BN statistics: stage-2 reduce over CTAs, then finalize (all fixed order)
// ---------------------------------------------------------------------------
__global__ __launch_bounds__(128) void stats_reduce_kernel(int ncta)
{
    int col = threadIdx.x;            // 0..127 (s|ss concatenated)
    float acc = 0.f;
    for (int p = blockIdx.x; p < ncta; p += 128)
        acc += g_stat[(size_t)p * 128 + col];
    g_part[blockIdx.x * 128 + col] = acc;
}

__global__ void stats_final_kernel(const float* __restrict__ gamma,
                                   const float* __restrict__ beta)
{
    int c = threadIdx.x;
    if (c >= 64) return;
    float s = 0.f, ss = 0.f;
    for (int p = 0; p < 128; p++) {
        s  += g_part[p * 128 + c];
        ss += g_part[p * 128 + 64 + c];
    }
    const float inv = 1.0f / (float)M_CONV;
    float mean = s * inv;
    float var  = fmaxf(ss * inv - mean * mean, 0.f);
    float sc   = gamma[c] * rsqrtf(var + 1e-5f);
    g_bn[c]      = sc;
    g_bn[64 + c] = beta[c] - mean * sc;
}

// Final in-place bn2 + lrelu on d_out
__global__ __launch_bounds__(256) void bn_act_kernel(float* __restrict__ y)
{
    size_t idx = (size_t)blockIdx.x * 256 + threadIdx.x;
    if (idx >= (size_t)M_CONV * 16) return;
    int c = ((int)idx & 15) * 4;
    float4 v = ((float4*)y)[idx];
    v.x = v.x * g_bn[c+0] + g_bn[64+c+0]; v.x = fmaxf(v.x, 0.2f * v.x);
    v.y = v.y * g_bn[c+1] + g_bn[64+c+1]; v.y = fmaxf(v.y, 0.2f * v.y);
    v.z = v.z * g_bn[c+2] + g_bn[64+c+2]; v.z = fmaxf(v.z, 0.2f * v.z);
    v.w = v.w * g_bn[c+3] + g_bn[64+c+3]; v.w = fmaxf(v.w, 0.2f * v.w);
    ((float4*)y)[idx] = v;
}

// ---------------------------------------------------------------------------
extern "C" void kernel_launch(void* const* d_in, const int* in_sizes, int n_in,
                              void* d_out, int out_size)
{
    const float* x1    = (const float*)d_in[0];
    const float* x2    = (const float*)d_in[1];
    const int*   neigh = (const int*)  d_in[2];
    const int*   topi  = (const int*)  d_in[3];
    const int*   downi = (const int*)  d_in[4];
    const float* up_W  = (const float*)d_in[5];
    const float* up_b  = (const float*)d_in[6];
    const float* w1    = (const float*)d_in[7];
    const float* b1    = (const float*)d_in[8];
    const float* g1    = (const float*)d_in[9];
    const float* be1   = (const float*)d_in[10];
    const float* w2    = (const float*)d_in[11];
    const float* b2    = (const float*)d_in[12];
    const float* g2    = (const float*)d_in[13];
    const float* be2   = (const float*)d_in[14];
    float* out = (float*)d_out;

    void *p_x1c, *p_h, *p_xcc, *p_y1, *p_y2c, *p_wuc, *p_w1c, *p_w2c;
    cudaGetSymbolAddress(&p_x1c, g_x1c);
    cudaGetSymbolAddress(&p_h,   g_h);
    cudaGetSymbolAddress(&p_xcc, g_xcc);
    cudaGetSymbolAddress(&p_y1,  g_y1);
    cudaGetSymbolAddress(&p_y2c, g_y2c);
    cudaGetSymbolAddress(&p_wuc, g_wuc);
    cudaGetSymbolAddress(&p_w1c, g_w1c);
    cudaGetSymbolAddress(&p_w2c, g_w2c);

    // Opt-in dynamic smem (idempotent; host-side config, not a stream op)
    cudaFuncSetAttribute(mma_gemm<128, 1, false, false>,
                         cudaFuncAttributeMaxDynamicSharedMemorySize, SMEM_DYN);
    cudaFuncSetAttribute(mma_gemm<128, 7, true, true>,
                         cudaFuncAttributeMaxDynamicSharedMemorySize, SMEM_DYN);
    cudaFuncSetAttribute(mma_gemm<64, 7, true, true>,
                         cudaFuncAttributeMaxDynamicSharedMemorySize, SMEM_DYN);

    // 0) weight transpose+split, x1 split
    tspl_kernel<<<(128*448 + 255)/256, 256>>>(up_W, (__nv_bfloat16*)p_wuc, 128, 448);
    tspl_kernel<<<(896*64  + 255)/256, 256>>>(w1,   (__nv_bfloat16*)p_w1c, 896, 64);
    tspl_kernel<<<(448*64  + 255)/256, 256>>>(w2,   (__nv_bfloat16*)p_w2c, 448, 64);
    x1split_kernel<<<(int)(((size_t)M_UP*32 + 255)/256), 256>>>(x1);

    // 1) up GEMM: [M_UP x 448] = x1 @ up_W + up_b
    mma_gemm<128, 1, false, false><<<dim3((M_UP + 127)/128, 7), 256, SMEM_DYN>>>(
        (const __nv_bfloat16*)p_x1c, (const __nv_bfloat16*)p_wuc,
        nullptr, up_b, (float*)p_h, M_UP, 448);

    // 2) upconv gather + concat + split
    build_xcat_kernel<<<(int)(((size_t)M_CONV*32 + 255)/256), 256>>>(x2, topi, downi);

    // 3) conv1 (gather GEMM, K=896) -> g_y1 (pre-BN) + fused stats partials
    mma_gemm<128, 7, true, true><<<dim3(NCTA_CONV, 1), 256, SMEM_DYN>>>(
        (const __nv_bfloat16*)p_xcc, (const __nv_bfloat16*)p_w1c,
        neigh, b1, (float*)p_y1, M_CONV, 64);

    // 4) bn1 stats finalize + split input for conv2
    stats_reduce_kernel<<<128, 128>>>(NCTA_CONV);
    stats_final_kernel<<<1, 64>>>(g1, be1);
    bn_split_kernel<<<(int)(((size_t)M_CONV*16 + 255)/256), 256>>>();

    // 5) conv2 (gather GEMM, K=448) -> d_out (pre-BN) + fused stats partials
    mma_gemm<64, 7, true, true><<<dim3(NCTA_CONV, 1), 256, SMEM_DYN>>>(
        (const __nv_bfloat16*)p_y2c, (const __nv_bfloat16*)p_w2c,
        neigh, b2, out, M_CONV, 64);

    // 6) bn2 stats finalize + final activation in place
    stats_reduce_kernel<<<128, 128>>>(NCTA_CONV);
    stats_final_kernel<<<1, 64>>>(g2, be2);
    bn_act_kernel<<<(int)(((size_t)M_CONV*16 + 255)/256), 256>>>(out);
}